// round 1
// baseline (speedup 1.0000x reference)
#include <cuda_runtime.h>

// RadiosityPropagater — N=4096 surfels, 64 tail lights, 3 bounces.
// Bounce 1 gathers only from the 64 light columns (B0 = emissions is zero
// elsewhere). Bounces 2,3 are full O(N^2) recomputed form-factor gathers.
// No atomics: j-split partials go to private slots, reduced in combine.

#define NMAX    4096
#define NLIGHTS 64
#define JSPLIT  32
#define JT_FULL 128
#define JT_L    64
#define BLK     256

__device__ float g_area[NMAX];                 // s0*s1*geo*nf  (= area_j / pi)
__device__ float g_part[JSPLIT * NMAX * 3];    // per-jsplit partial gathers
__device__ float g_B[NMAX * 3];                // radiosity between bounces

__global__ void prep_kernel(const float* __restrict__ scales,
                            const float* __restrict__ geo,
                            const float* __restrict__ nf, int N) {
    int i = blockIdx.x * blockDim.x + threadIdx.x;
    if (i < N) g_area[i] = scales[3*i] * scales[3*i+1] * geo[i] * nf[i];
}

// One block: BLK receivers (i) x JT emitters (j). Emitter data staged in smem
// as 3 vector words per j (float4 + float4 + float2) so the inner loop issues
// only 3 broadcast LDS per iteration. Partial sum written (no atomics) to
// g_part[blockIdx.y].
template<int JT, bool BIN_IS_GB>
__global__ void pair_kernel(const float* __restrict__ means,
                            const float* __restrict__ normals,
                            const float* __restrict__ BinExt,
                            int N, int jbase) {
    __shared__ float4 sA[JT];   // mx, my, mz, area
    __shared__ float4 sB[JT];   // nx, ny, nz, b0
    __shared__ float2 sC[JT];   // b1, b2

    const float* Bin = BIN_IS_GB ? g_B : BinExt;
    int tid = threadIdx.x;
    int j0  = jbase + blockIdx.y * JT;

    for (int j = tid; j < JT; j += blockDim.x) {
        int jg = j0 + j;
        sA[j] = make_float4(means[3*jg], means[3*jg+1], means[3*jg+2], g_area[jg]);
        sB[j] = make_float4(normals[3*jg], normals[3*jg+1], normals[3*jg+2], Bin[3*jg]);
        sC[j] = make_float2(Bin[3*jg+1], Bin[3*jg+2]);
    }
    __syncthreads();

    int i = blockIdx.x * blockDim.x + tid;
    float rx = means[3*i],   ry = means[3*i+1],   rz = means[3*i+2];
    float nx = normals[3*i], ny = normals[3*i+1], nz = normals[3*i+2];

    float a0 = 0.f, a1 = 0.f, a2 = 0.f;
    #pragma unroll 8
    for (int j = 0; j < JT; j++) {
        float4 A  = sA[j];
        float4 Bv = sB[j];
        float2 C  = sC[j];
        float dx = A.x - rx, dy = A.y - ry, dz = A.z - rz;
        float d2 = fmaf(dx, dx, fmaf(dy, dy, fmaf(dz, dz, 1e-8f)));
        float invd  = rsqrtf(d2);
        float invd2 = invd * invd;                       // ~ 1/d2
        // relu(dot)*invd == relu(dot*invd) since invd > 0
        float pi_ = fmaxf(fmaf(dx, nx,   fmaf(dy, ny,   dz * nz)),   0.f);
        float pj_ = fmaxf(-fmaf(dx, Bv.x, fmaf(dy, Bv.y, dz * Bv.z)), 0.f);
        float fall = fminf(fmaxf(invd2, 1e-4f), 1.0f);
        float w = pi_ * pj_ * invd2 * fall * A.w;
        w = (j0 + j == i) ? 0.f : w;                     // no self-transport
        a0 = fmaf(w, Bv.w, a0);
        a1 = fmaf(w, C.x,  a1);
        a2 = fmaf(w, C.y,  a2);
    }

    float* p = g_part + (size_t)blockIdx.y * N * 3 + 3 * i;
    p[0] = a0; p[1] = a1; p[2] = a2;
}

__global__ void combine_kernel(const float* __restrict__ emis,
                               const float* __restrict__ brdf,
                               int N, int nsplit, int isFinal,
                               float* __restrict__ out) {
    int i = blockIdx.x * blockDim.x + threadIdx.x;
    if (i >= N) return;
    float g0 = 0.f, g1 = 0.f, g2 = 0.f;
    for (int s = 0; s < nsplit; s++) {
        const float* p = g_part + (size_t)s * N * 3 + 3 * i;
        g0 += p[0]; g1 += p[1]; g2 += p[2];
    }
    bool light = (i >= N - NLIGHTS);
    float e0 = emis[3*i], e1 = emis[3*i+1], e2 = emis[3*i+2];
    float b0 = light ? e0 : fmaf(brdf[3*i],   g0, e0);
    float b1 = light ? e1 : fmaf(brdf[3*i+1], g1, e1);
    float b2 = light ? e2 : fmaf(brdf[3*i+2], g2, e2);
    if (isFinal) {
        out[3*i]   = fmaxf(b0, 0.f);
        out[3*i+1] = fmaxf(b1, 0.f);
        out[3*i+2] = fmaxf(b2, 0.f);
    } else {
        g_B[3*i] = b0; g_B[3*i+1] = b1; g_B[3*i+2] = b2;
    }
}

extern "C" void kernel_launch(void* const* d_in, const int* in_sizes, int n_in,
                              void* d_out, int out_size) {
    const float* means   = (const float*)d_in[0];
    const float* geo     = (const float*)d_in[1];
    const float* scales  = (const float*)d_in[2];
    // d_in[3] = rots — unused (API parity only, per reference)
    const float* normals = (const float*)d_in[4];
    const float* nf      = (const float*)d_in[5];
    const float* emis    = (const float*)d_in[6];
    const float* brdf    = (const float*)d_in[7];
    float* out = (float*)d_out;

    int N = in_sizes[1];          // geovalues count = 4096
    int nIB = N / BLK;            // 16 i-tiles

    prep_kernel<<<(N + BLK - 1) / BLK, BLK>>>(scales, geo, nf, N);

    // Bounce 1: B0 = emissions, nonzero only on tail NLIGHTS columns
    pair_kernel<JT_L, false><<<dim3(nIB, 1), BLK>>>(means, normals, emis, N, N - NLIGHTS);
    combine_kernel<<<(N + BLK - 1) / BLK, BLK>>>(emis, brdf, N, 1, 0, out);

    // Bounce 2: full gather from g_B
    pair_kernel<JT_FULL, true><<<dim3(nIB, JSPLIT), BLK>>>(means, normals, nullptr, N, 0);
    combine_kernel<<<(N + BLK - 1) / BLK, BLK>>>(emis, brdf, N, JSPLIT, 0, out);

    // Bounce 3: full gather, final relu -> d_out
    pair_kernel<JT_FULL, true><<<dim3(nIB, JSPLIT), BLK>>>(means, normals, nullptr, N, 0);
    combine_kernel<<<(N + BLK - 1) / BLK, BLK>>>(emis, brdf, N, JSPLIT, 1, out);
}

// round 2
// speedup vs baseline: 1.3105x; 1.3105x over previous
#include <cuda_runtime.h>
#include <cuda_fp16.h>

// RadiosityPropagater — N=4096 surfels, 64 tail lights, 3 bounces.
//  bounce1: sparse gather over the 64 light columns (B0 zero elsewhere), combine fused.
//  bounce2: full O(N^2) pass; computes form-factor weights, gathers with B1,
//           AND materializes F_T[j][i] (fp16, x1024) for reuse.
//  bounce3: memory-bound matvec over F_T (32MB), combine separate.
// No atomics anywhere: j-split partials in private slots, reduced deterministically.

#define NMAX    4096
#define NLIGHTS 64
#define BLK     256
#define ITILE   2
#define JT2     128
#define JS2     (NMAX / JT2)       // 32
#define JT3     64
#define JS3     (NMAX / JT3)       // 64
#define IT3     4
#define FSCALE  1024.0f
#define INV_S   (1.0f / 1024.0f)

__device__ float4 g_snf4[NMAX];                 // emitter normal * area * 1024
__device__ float  g_part[JS3 * NMAX * 3];       // per-split partial gathers
__device__ float  g_B[NMAX * 3];                // radiosity between bounces
__device__ __half g_F[(size_t)NMAX * NMAX];     // F_T[j][i] = 1024 * F[i][j]

__device__ __forceinline__ float frcp(float x) {
    float r;
    asm("rcp.approx.ftz.f32 %0, %1;" : "=f"(r) : "f"(x));
    return r;
}

__global__ void prep_kernel(const float* __restrict__ scales,
                            const float* __restrict__ geo,
                            const float* __restrict__ nf,
                            const float* __restrict__ normals, int N) {
    int i = blockIdx.x * blockDim.x + threadIdx.x;
    if (i < N) {
        float a = scales[3*i] * scales[3*i+1] * geo[i] * nf[i] * FSCALE;
        g_snf4[i] = make_float4(normals[3*i] * a, normals[3*i+1] * a,
                                normals[3*i+2] * a, 0.f);
    }
}

// Bounce 1: gather from the 64 tail light columns only; combine fused.
__global__ void bounce1_kernel(const float* __restrict__ means,
                               const float* __restrict__ normals,
                               const float* __restrict__ emis,
                               const float* __restrict__ brdf, int N) {
    __shared__ float4 sM[NLIGHTS];   // m.xyz, b0'
    __shared__ float4 sS[NLIGHTS];   // sn.xyz, b1'
    __shared__ float  sC[NLIGHTS];   // b2'
    int tid = threadIdx.x;
    int jbase = N - NLIGHTS;
    if (tid < NLIGHTS) {
        int jg = jbase + tid;
        float4 sn = g_snf4[jg];
        sM[tid] = make_float4(means[3*jg], means[3*jg+1], means[3*jg+2],
                              emis[3*jg] * INV_S);
        sS[tid] = make_float4(sn.x, sn.y, sn.z, emis[3*jg+1] * INV_S);
        sC[tid] = emis[3*jg+2] * INV_S;
    }
    __syncthreads();

    int i = blockIdx.x * blockDim.x + tid;
    float rx = means[3*i],   ry = means[3*i+1],   rz = means[3*i+2];
    float nx = normals[3*i], ny = normals[3*i+1], nz = normals[3*i+2];
    float a0 = 0.f, a1 = 0.f, a2 = 0.f;
    #pragma unroll 8
    for (int j = 0; j < NLIGHTS; j++) {
        float4 M = sM[j]; float4 S = sS[j]; float c = sC[j];
        float dx = M.x - rx, dy = M.y - ry, dz = M.z - rz;
        float d2 = fmaf(dx, dx, fmaf(dy, dy, fmaf(dz, dz, 1e-8f)));
        float r  = frcp(d2);
        float rf = r * fminf(fmaxf(r, 1e-4f), 1.0f);
        float pi_ = fmaxf(fmaf(dx, nx,  fmaf(dy, ny,  dz * nz)),  0.f);
        float pj_ = fmaxf(-fmaf(dx, S.x, fmaf(dy, S.y, dz * S.z)), 0.f);
        float w = pi_ * (pj_ * rf);
        a0 = fmaf(w, M.w, a0);
        a1 = fmaf(w, S.w, a1);
        a2 = fmaf(w, c,   a2);
    }
    bool light = (i >= N - NLIGHTS);
    float e0 = emis[3*i], e1 = emis[3*i+1], e2 = emis[3*i+2];
    g_B[3*i]   = light ? e0 : fmaf(brdf[3*i],   a0, e0);
    g_B[3*i+1] = light ? e1 : fmaf(brdf[3*i+1], a1, e1);
    g_B[3*i+2] = light ? e2 : fmaf(brdf[3*i+2], a2, e2);
}

// Bounce 2: full pass. Each thread handles two ADJACENT receivers (i0, i0+1)
// so the fp16 F_T store is one coalesced half2 per j. Gather partials per
// j-split go to private slots.
__global__ void __launch_bounds__(BLK) pass_build_kernel(
        const float* __restrict__ means,
        const float* __restrict__ normals, int N) {
    __shared__ float4 sM[JT2];
    __shared__ float4 sS[JT2];
    __shared__ float  sC[JT2];
    int tid = threadIdx.x;
    int j0  = blockIdx.y * JT2;
    for (int j = tid; j < JT2; j += BLK) {
        int jg = j0 + j;
        float4 sn = g_snf4[jg];
        sM[j] = make_float4(means[3*jg], means[3*jg+1], means[3*jg+2],
                            g_B[3*jg] * INV_S);
        sS[j] = make_float4(sn.x, sn.y, sn.z, g_B[3*jg+1] * INV_S);
        sC[j] = g_B[3*jg+2] * INV_S;
    }
    __syncthreads();

    int i0 = blockIdx.x * (BLK * ITILE) + 2 * tid;
    float rx0 = means[3*i0],   ry0 = means[3*i0+1],   rz0 = means[3*i0+2];
    float nx0 = normals[3*i0], ny0 = normals[3*i0+1], nz0 = normals[3*i0+2];
    float rx1 = means[3*i0+3], ry1 = means[3*i0+4],   rz1 = means[3*i0+5];
    float nx1 = normals[3*i0+3], ny1 = normals[3*i0+4], nz1 = normals[3*i0+5];

    float a00=0.f,a01=0.f,a02=0.f, a10=0.f,a11=0.f,a12=0.f;
    __half* fp = g_F + (size_t)j0 * N + i0;

    #pragma unroll 4
    for (int j = 0; j < JT2; j++) {
        float4 M = sM[j]; float4 S = sS[j]; float c = sC[j];
        // receiver i0
        float dx = M.x - rx0, dy = M.y - ry0, dz = M.z - rz0;
        float d2 = fmaf(dx, dx, fmaf(dy, dy, fmaf(dz, dz, 1e-8f)));
        float r  = frcp(d2);
        float rf = r * fminf(fmaxf(r, 1e-4f), 1.0f);
        float pi_ = fmaxf(fmaf(dx, nx0, fmaf(dy, ny0, dz * nz0)), 0.f);
        float pj_ = fmaxf(-fmaf(dx, S.x, fmaf(dy, S.y, dz * S.z)), 0.f);
        float w0 = pi_ * (pj_ * rf);
        // receiver i0+1
        dx = M.x - rx1; dy = M.y - ry1; dz = M.z - rz1;
        d2 = fmaf(dx, dx, fmaf(dy, dy, fmaf(dz, dz, 1e-8f)));
        r  = frcp(d2);
        rf = r * fminf(fmaxf(r, 1e-4f), 1.0f);
        pi_ = fmaxf(fmaf(dx, nx1, fmaf(dy, ny1, dz * nz1)), 0.f);
        pj_ = fmaxf(-fmaf(dx, S.x, fmaf(dy, S.y, dz * S.z)), 0.f);
        float w1 = pi_ * (pj_ * rf);

        a00 = fmaf(w0, M.w, a00); a01 = fmaf(w0, S.w, a01); a02 = fmaf(w0, c, a02);
        a10 = fmaf(w1, M.w, a10); a11 = fmaf(w1, S.w, a11); a12 = fmaf(w1, c, a12);

        *(__half2*)(fp) = __floats2half2_rn(w0, w1);   // F_T[j0+j][i0..i0+1]
        fp += N;
    }

    float* p = g_part + (size_t)blockIdx.y * N * 3;
    p[3*i0]   = a00; p[3*i0+1] = a01; p[3*i0+2] = a02;
    p[3*i0+3] = a10; p[3*i0+4] = a11; p[3*i0+5] = a12;
}

__global__ void combine_kernel(const float* __restrict__ emis,
                               const float* __restrict__ brdf,
                               int N, int nsplit, int isFinal,
                               float* __restrict__ out) {
    int i = blockIdx.x * blockDim.x + threadIdx.x;
    if (i >= N) return;
    float g0 = 0.f, g1 = 0.f, g2 = 0.f;
    for (int s = 0; s < nsplit; s++) {
        const float* p = g_part + (size_t)s * N * 3 + 3 * i;
        g0 += p[0]; g1 += p[1]; g2 += p[2];
    }
    bool light = (i >= N - NLIGHTS);
    float e0 = emis[3*i], e1 = emis[3*i+1], e2 = emis[3*i+2];
    float b0 = light ? e0 : fmaf(brdf[3*i],   g0, e0);
    float b1 = light ? e1 : fmaf(brdf[3*i+1], g1, e1);
    float b2 = light ? e2 : fmaf(brdf[3*i+2], g2, e2);
    if (isFinal) {
        out[3*i]   = fmaxf(b0, 0.f);
        out[3*i+1] = fmaxf(b1, 0.f);
        out[3*i+2] = fmaxf(b2, 0.f);
    } else {
        g_B[3*i] = b0; g_B[3*i+1] = b1; g_B[3*i+2] = b2;
    }
}

// Bounce 3: matvec over stored fp16 F_T. Each thread owns 4 consecutive i,
// loops over a 64-j tile with B2/1024 staged in smem (broadcast LDS.128).
__global__ void __launch_bounds__(BLK) matvec_kernel(int N) {
    __shared__ float4 sB[JT3];
    int tid = threadIdx.x;
    int j0 = blockIdx.y * JT3;
    for (int j = tid; j < JT3; j += BLK) {
        int jg = j0 + j;
        sB[j] = make_float4(g_B[3*jg] * INV_S, g_B[3*jg+1] * INV_S,
                            g_B[3*jg+2] * INV_S, 0.f);
    }
    __syncthreads();

    int i0 = (blockIdx.x * BLK + tid) * IT3;
    float c00=0.f,c01=0.f,c02=0.f, c10=0.f,c11=0.f,c12=0.f;
    float c20=0.f,c21=0.f,c22=0.f, c30=0.f,c31=0.f,c32=0.f;

    const __half* fp = g_F + (size_t)j0 * N + i0;
    #pragma unroll 4
    for (int j = 0; j < JT3; j++) {
        float4 b = sB[j];
        uint2 wv = *(const uint2*)(fp);
        fp += N;
        float2 f0 = __half22float2(*(const __half2*)&wv.x);
        float2 f1 = __half22float2(*(const __half2*)&wv.y);
        c00 = fmaf(f0.x, b.x, c00); c01 = fmaf(f0.x, b.y, c01); c02 = fmaf(f0.x, b.z, c02);
        c10 = fmaf(f0.y, b.x, c10); c11 = fmaf(f0.y, b.y, c11); c12 = fmaf(f0.y, b.z, c12);
        c20 = fmaf(f1.x, b.x, c20); c21 = fmaf(f1.x, b.y, c21); c22 = fmaf(f1.x, b.z, c22);
        c30 = fmaf(f1.y, b.x, c30); c31 = fmaf(f1.y, b.y, c31); c32 = fmaf(f1.y, b.z, c32);
    }

    float* p = g_part + (size_t)blockIdx.y * N * 3 + 3 * i0;
    ((float4*)p)[0] = make_float4(c00, c01, c02, c10);
    ((float4*)p)[1] = make_float4(c11, c12, c20, c21);
    ((float4*)p)[2] = make_float4(c22, c30, c31, c32);
}

extern "C" void kernel_launch(void* const* d_in, const int* in_sizes, int n_in,
                              void* d_out, int out_size) {
    const float* means   = (const float*)d_in[0];
    const float* geo     = (const float*)d_in[1];
    const float* scales  = (const float*)d_in[2];
    // d_in[3] = rots — unused (API parity only, per reference)
    const float* normals = (const float*)d_in[4];
    const float* nf      = (const float*)d_in[5];
    const float* emis    = (const float*)d_in[6];
    const float* brdf    = (const float*)d_in[7];
    float* out = (float*)d_out;

    int N = in_sizes[1];              // 4096
    int nIB = (N + BLK - 1) / BLK;    // 16

    prep_kernel<<<nIB, BLK>>>(scales, geo, nf, normals, N);

    // Bounce 1 (sparse, combine fused) -> g_B
    bounce1_kernel<<<nIB, BLK>>>(means, normals, emis, brdf, N);

    // Bounce 2: build F_T + gather
    pass_build_kernel<<<dim3(N / (BLK * ITILE), JS2), BLK>>>(means, normals, N);
    combine_kernel<<<nIB, BLK>>>(emis, brdf, N, JS2, 0, out);

    // Bounce 3: matvec over F_T, final relu -> d_out
    matvec_kernel<<<dim3(N / (BLK * IT3), JS3), BLK>>>(N);
    combine_kernel<<<nIB, BLK>>>(emis, brdf, N, JS3, 1, out);
}